// round 1
// baseline (speedup 1.0000x reference)
#include <cuda_runtime.h>
#include <math.h>
#include <stdint.h>

// Problem constants
#define B_  8
#define S_  1024
#define D_  512
#define H_  8
#define DH  64
#define FF_ 2048
#define L_  6
#define M_  (B_*S_)   // 8192 rows

// ---------------- scratch (static device globals; no allocation) ----------------
__device__ float g_x[M_*D_];        // current activations [8192,512]
__device__ float g_qkv[M_*3*D_];    // qkv buffer [8192,1536]
__device__ float g_att[M_*D_];      // attention output
__device__ float g_h[M_*FF_];       // ffn hidden [8192,2048]
__device__ float g_t[M_*D_];        // pre-LN temp
__device__ int   g_pos[M_];         // positions from mask cumsum

// ============================================================================
// Position scan: positions = cumsum(mask!=0, axis=1) * (mask!=0)
// ============================================================================
__global__ void pos_scan_kernel(const int* __restrict__ mask)
{
    __shared__ int sc[S_];
    int b = blockIdx.x;
    int t = threadIdx.x;
    int v = (mask[b*S_ + t] != 0) ? 1 : 0;
    sc[t] = v;
    __syncthreads();
    for (int off = 1; off < S_; off <<= 1) {
        int add = (t >= off) ? sc[t - off] : 0;
        __syncthreads();
        sc[t] += add;
        __syncthreads();
    }
    g_pos[b*S_ + t] = v ? sc[t] : 0;
}

// ============================================================================
// x = x_in + sinusoidal_table[pos]  (padding pos=0 -> zero row)
// ============================================================================
__global__ void add_pos_kernel(const float* __restrict__ xin)
{
    int idx = blockIdx.x * 256 + threadIdx.x;   // over M_*D_ = 4194304
    int d = idx & (D_-1);
    int row = idx >> 9;                          // b*S + s
    int pos = g_pos[row];
    float e = 0.f;
    if (pos > 0) {
        const float c = -9.210340371976184f / 255.0f;  // -ln(10000)/(half-1)
        if (d < 256) e = sinf((float)pos * expf((float)d * c));
        else         e = cosf((float)pos * expf((float)(d - 256) * c));
    }
    g_x[idx] = xin[idx] + e;
}

// ============================================================================
// SGEMM: C[M,N] = A[M,K] @ B[K,N] (+bias[N]) (+Res[M,N]) (+relu)
// 128x128 block tile, BK=8, 256 threads, 8x8 microtile.
// ============================================================================
template<bool BIAS, bool RELU, bool RES>
__global__ void __launch_bounds__(256)
sgemm_kernel(const float* __restrict__ A, const float* __restrict__ Bw,
             const float* __restrict__ bias, const float* __restrict__ Res,
             float* __restrict__ C, int M, int N, int K)
{
    __shared__ float As[8][128];
    __shared__ float Bs[8][128];

    const int tid = threadIdx.x;
    const int bx = blockIdx.x, by = blockIdx.y;
    const int tx = tid & 15, ty = tid >> 4;

    const int row_a = tid >> 1;            // 0..127
    const int ca    = (tid & 1) * 4;       // 0 or 4
    const int row_b = tid >> 5;            // 0..7
    const int cb    = (tid & 31) * 4;      // 0..124

    const float* Aptr = A + (size_t)(by*128 + row_a)*K + ca;
    const float* Bptr = Bw + (size_t)row_b*N + (size_t)bx*128 + cb;

    float acc[8][8];
    #pragma unroll
    for (int i = 0; i < 8; i++)
        #pragma unroll
        for (int j = 0; j < 8; j++) acc[i][j] = 0.f;

    for (int k0 = 0; k0 < K; k0 += 8) {
        float4 av = *(const float4*)(Aptr + k0);
        float4 bv = *(const float4*)(Bptr + (size_t)k0 * N);
        __syncthreads();
        As[ca+0][row_a] = av.x;
        As[ca+1][row_a] = av.y;
        As[ca+2][row_a] = av.z;
        As[ca+3][row_a] = av.w;
        *(float4*)&Bs[row_b][cb] = bv;
        __syncthreads();

        #pragma unroll
        for (int kk = 0; kk < 8; kk++) {
            float4 a0 = *(const float4*)&As[kk][ty*4];
            float4 a1 = *(const float4*)&As[kk][64 + ty*4];
            float4 b0 = *(const float4*)&Bs[kk][tx*4];
            float4 b1 = *(const float4*)&Bs[kk][64 + tx*4];
            float ar[8] = {a0.x,a0.y,a0.z,a0.w,a1.x,a1.y,a1.z,a1.w};
            float br[8] = {b0.x,b0.y,b0.z,b0.w,b1.x,b1.y,b1.z,b1.w};
            #pragma unroll
            for (int i = 0; i < 8; i++)
                #pragma unroll
                for (int j = 0; j < 8; j++)
                    acc[i][j] += ar[i] * br[j];
        }
    }

    // epilogue
    #pragma unroll
    for (int i = 0; i < 8; i++) {
        int gr = by*128 + ((i < 4) ? (ty*4 + i) : (64 + ty*4 + i - 4));
        #pragma unroll
        for (int gcol = 0; gcol < 2; gcol++) {
            int gc = bx*128 + gcol*64 + tx*4;
            float4 v;
            v.x = acc[i][gcol*4+0]; v.y = acc[i][gcol*4+1];
            v.z = acc[i][gcol*4+2]; v.w = acc[i][gcol*4+3];
            if (BIAS) {
                float4 bb = *(const float4*)&bias[gc];
                v.x += bb.x; v.y += bb.y; v.z += bb.z; v.w += bb.w;
            }
            if (RES) {
                float4 rr = *(const float4*)&Res[(size_t)gr*N + gc];
                v.x += rr.x; v.y += rr.y; v.z += rr.z; v.w += rr.w;
            }
            if (RELU) {
                v.x = fmaxf(v.x, 0.f); v.y = fmaxf(v.y, 0.f);
                v.z = fmaxf(v.z, 0.f); v.w = fmaxf(v.w, 0.f);
            }
            *(float4*)&C[(size_t)gr*N + gc] = v;
        }
    }
}

// ============================================================================
// Flash attention: per (b,h), 64-query tile per block, online softmax.
// q/k/v live interleaved in g_qkv rows of 1536. scale = 1.
// ============================================================================
#define KQ_LD 68   // padded stride for transposed-store buffers

__global__ void __launch_bounds__(256)
attn_kernel(const float* __restrict__ qkv, const int* __restrict__ mask,
            float* __restrict__ out)
{
    extern __shared__ float sm[];
    float* QsT = sm;                   // [64 dh][KQ_LD]  QsT[d][q]
    float* KsT = QsT + 64*KQ_LD;       // [64 dh][KQ_LD]  KsT[d][kv]
    float* Vs  = KsT + 64*KQ_LD;       // [64 kv][64 d]
    float* Ps  = Vs  + 64*64;          // [64 kv][64 q]
    float* m_s = Ps  + 64*64;          // [64]
    float* l_s = m_s + 64;             // [64]
    float* c_s = l_s + 64;             // [64]
    int*   kvm = (int*)(c_s + 64);     // [64]

    const int tid = threadIdx.x;
    const int tx = tid & 15, ty = tid >> 4;
    const int q0 = blockIdx.x * 64;
    const int b  = blockIdx.y >> 3;
    const int h  = blockIdx.y & 7;
    const int RS = 3 * D_;             // qkv row stride

    const float* qbase  = qkv + ((size_t)(b*S_ + q0))*RS + h*DH;
    const float* kbase0 = qkv + ((size_t)b*S_)*RS + D_   + h*DH;
    const float* vbase0 = qkv + ((size_t)b*S_)*RS + 2*D_ + h*DH;

    // load Q tile transposed: QsT[d][q]
    #pragma unroll
    for (int i = 0; i < 16; i++) {
        int idx = i*256 + tid;
        int r = idx >> 6, d = idx & 63;
        QsT[d*KQ_LD + r] = qbase[(size_t)r*RS + d];
    }
    if (tid < 64) { m_s[tid] = -INFINITY; l_s[tid] = 0.f; }

    float o[4][4];                     // q rows ty*4+ii, dims tx*4+jj
    #pragma unroll
    for (int ii = 0; ii < 4; ii++)
        #pragma unroll
        for (int jj = 0; jj < 4; jj++) o[ii][jj] = 0.f;

    for (int j = 0; j < S_/64; j++) {
        __syncthreads();  // previous tile's PV/softmax done before overwrite
        const float* kb = kbase0 + (size_t)(j*64)*RS;
        const float* vb = vbase0 + (size_t)(j*64)*RS;
        #pragma unroll
        for (int i = 0; i < 16; i++) {
            int idx = i*256 + tid;
            int r = idx >> 6, d = idx & 63;
            KsT[d*KQ_LD + r] = kb[(size_t)r*RS + d];
            Vs[r*64 + d]     = vb[(size_t)r*RS + d];
        }
        if (tid < 64) kvm[tid] = mask[b*S_ + j*64 + tid];
        __syncthreads();

        // S' = K Q^T : rows kv = ty*4+ii, cols q = tx*4+jj
        float s[4][4];
        #pragma unroll
        for (int ii = 0; ii < 4; ii++)
            #pragma unroll
            for (int jj = 0; jj < 4; jj++) s[ii][jj] = 0.f;
        #pragma unroll
        for (int k = 0; k < 64; k++) {
            float4 a = *(const float4*)&KsT[k*KQ_LD + ty*4];
            float4 q = *(const float4*)&QsT[k*KQ_LD + tx*4];
            float ar[4] = {a.x,a.y,a.z,a.w};
            float qr[4] = {q.x,q.y,q.z,q.w};
            #pragma unroll
            for (int ii = 0; ii < 4; ii++)
                #pragma unroll
                for (int jj = 0; jj < 4; jj++)
                    s[ii][jj] += ar[ii] * qr[jj];
        }
        #pragma unroll
        for (int ii = 0; ii < 4; ii++) {
            if (kvm[ty*4 + ii] == 0) {
                s[ii][0] = -INFINITY; s[ii][1] = -INFINITY;
                s[ii][2] = -INFINITY; s[ii][3] = -INFINITY;
            }
            float4 w; w.x=s[ii][0]; w.y=s[ii][1]; w.z=s[ii][2]; w.w=s[ii][3];
            *(float4*)&Ps[(ty*4+ii)*64 + tx*4] = w;
        }
        __syncthreads();

        // online softmax per q row (64 worker threads)
        if (tid < 64) {
            int r = tid;
            float mo = m_s[r];
            float tm = -INFINITY;
            #pragma unroll 8
            for (int kv = 0; kv < 64; kv++) tm = fmaxf(tm, Ps[kv*64 + r]);
            float mn = fmaxf(mo, tm);
            float c, sum = 0.f;
            if (mn == -INFINITY) {
                c = 1.f;
                #pragma unroll 8
                for (int kv = 0; kv < 64; kv++) Ps[kv*64 + r] = 0.f;
            } else {
                c = __expf(mo - mn);
                #pragma unroll 8
                for (int kv = 0; kv < 64; kv++) {
                    float p = __expf(Ps[kv*64 + r] - mn);
                    Ps[kv*64 + r] = p;
                    sum += p;
                }
            }
            l_s[r] = l_s[r]*c + sum;
            m_s[r] = mn;
            c_s[r] = c;
        }
        __syncthreads();

        // rescale + O += P^T V  (P stored [kv][q])
        float cr[4];
        #pragma unroll
        for (int ii = 0; ii < 4; ii++) cr[ii] = c_s[ty*4 + ii];
        #pragma unroll
        for (int ii = 0; ii < 4; ii++)
            #pragma unroll
            for (int jj = 0; jj < 4; jj++) o[ii][jj] *= cr[ii];
        #pragma unroll
        for (int k = 0; k < 64; k++) {
            float4 p = *(const float4*)&Ps[k*64 + ty*4];
            float4 v = *(const float4*)&Vs[k*64 + tx*4];
            float pr[4] = {p.x,p.y,p.z,p.w};
            float vr[4] = {v.x,v.y,v.z,v.w};
            #pragma unroll
            for (int ii = 0; ii < 4; ii++)
                #pragma unroll
                for (int jj = 0; jj < 4; jj++)
                    o[ii][jj] += pr[ii] * vr[jj];
        }
    }

    // finalize: divide by l, write out[b, q0+r, h*64 + d]
    float inv[4];
    #pragma unroll
    for (int ii = 0; ii < 4; ii++) {
        float l = l_s[ty*4 + ii];
        inv[ii] = 1.f / l;
    }
    #pragma unroll
    for (int ii = 0; ii < 4; ii++) {
        float4 w;
        w.x = o[ii][0]*inv[ii]; w.y = o[ii][1]*inv[ii];
        w.z = o[ii][2]*inv[ii]; w.w = o[ii][3]*inv[ii];
        *(float4*)&out[((size_t)(b*S_ + q0 + ty*4 + ii))*D_ + h*DH + tx*4] = w;
    }
}

// ============================================================================
// LayerNorm over last dim (512). One block per row, 256 threads (float2 each).
// ============================================================================
__global__ void __launch_bounds__(256)
ln_kernel(const float* __restrict__ X, const float* __restrict__ g,
          const float* __restrict__ bta, float* __restrict__ Y)
{
    __shared__ float red[32];
    const int row = blockIdx.x;
    const int t = threadIdx.x;
    const int lane = t & 31, w = t >> 5;

    float2 v = ((const float2*)(X + (size_t)row*D_))[t];

    float s = v.x + v.y;
    #pragma unroll
    for (int o = 16; o; o >>= 1) s += __shfl_xor_sync(0xffffffffu, s, o);
    if (lane == 0) red[w] = s;
    __syncthreads();
    if (t < 32) {
        float a = (t < 8) ? red[t] : 0.f;
        #pragma unroll
        for (int o = 4; o; o >>= 1) a += __shfl_xor_sync(0xffffffffu, a, o);
        if (t == 0) red[0] = a;
    }
    __syncthreads();
    const float mu = red[0] * (1.f / D_);
    __syncthreads();

    float d0 = v.x - mu, d1 = v.y - mu;
    float q = d0*d0 + d1*d1;
    #pragma unroll
    for (int o = 16; o; o >>= 1) q += __shfl_xor_sync(0xffffffffu, q, o);
    if (lane == 0) red[w] = q;
    __syncthreads();
    if (t < 32) {
        float a = (t < 8) ? red[t] : 0.f;
        #pragma unroll
        for (int o = 4; o; o >>= 1) a += __shfl_xor_sync(0xffffffffu, a, o);
        if (t == 0) red[0] = a;
    }
    __syncthreads();
    const float var = red[0] * (1.f / D_);
    const float inv = rsqrtf(var + 1e-5f);

    float2 gv = ((const float2*)g)[t];
    float2 bv = ((const float2*)bta)[t];
    float2 o2;
    o2.x = d0 * inv * gv.x + bv.x;
    o2.y = d1 * inv * gv.y + bv.y;
    ((float2*)(Y + (size_t)row*D_))[t] = o2;
}

// ============================================================================
// Host launcher
// ============================================================================
extern "C" void kernel_launch(void* const* d_in, const int* in_sizes, int n_in,
                              void* d_out, int out_size)
{
    const float* x_in  = (const float*)d_in[0];
    // d_in[1]=char_ids (unused), d_in[2]=seq_len (unused)
    const int*   mask  = (const int*)d_in[3];
    const float* Wqkv  = (const float*)d_in[4];
    const float* Wfc   = (const float*)d_in[5];
    const float* bfc   = (const float*)d_in[6];
    const float* ln1g  = (const float*)d_in[7];
    const float* ln1b  = (const float*)d_in[8];
    const float* ln2g  = (const float*)d_in[9];
    const float* ln2b  = (const float*)d_in[10];
    const float* W1    = (const float*)d_in[11];
    const float* b1    = (const float*)d_in[12];
    const float* W2    = (const float*)d_in[13];
    const float* b2    = (const float*)d_in[14];
    float* out = (float*)d_out;

    float *px, *pqkv, *patt, *ph, *pt;
    cudaGetSymbolAddress((void**)&px,   g_x);
    cudaGetSymbolAddress((void**)&pqkv, g_qkv);
    cudaGetSymbolAddress((void**)&patt, g_att);
    cudaGetSymbolAddress((void**)&ph,   g_h);
    cudaGetSymbolAddress((void**)&pt,   g_t);

    const size_t attn_smem = (size_t)(64*KQ_LD*2 + 64*64*2 + 64*3) * sizeof(float)
                           + 64 * sizeof(int);
    cudaFuncSetAttribute(attn_kernel, cudaFuncAttributeMaxDynamicSharedMemorySize,
                         (int)attn_smem);

    // position embedding
    pos_scan_kernel<<<B_, S_>>>(mask);
    add_pos_kernel<<<(M_*D_)/256, 256>>>(x_in);

    for (int l = 0; l < L_; l++) {
        // qkv = x @ Wqkv[l]          [8192,512] x [512,1536]
        sgemm_kernel<false,false,false><<<dim3(1536/128, M_/128), 256>>>(
            px, Wqkv + (size_t)l*D_*3*D_, nullptr, nullptr, pqkv, M_, 3*D_, D_);

        // attention
        attn_kernel<<<dim3(S_/64, B_*H_), 256, attn_smem>>>(pqkv, mask, patt);

        // o @ Wfc + bfc + residual(x) -> t ; LN1 -> x
        sgemm_kernel<true,false,true><<<dim3(D_/128, M_/128), 256>>>(
            patt, Wfc + (size_t)l*D_*D_, bfc + (size_t)l*D_, px, pt, M_, D_, D_);
        ln_kernel<<<M_, 256>>>(pt, ln1g + (size_t)l*D_, ln1b + (size_t)l*D_, px);

        // h = relu(x @ W1 + b1)      [8192,512] x [512,2048]
        sgemm_kernel<true,true,false><<<dim3(FF_/128, M_/128), 256>>>(
            px, W1 + (size_t)l*D_*FF_, b1 + (size_t)l*FF_, nullptr, ph, M_, FF_, D_);

        // h @ W2 + b2 + residual(x) -> t ; LN2 -> x (or d_out on last layer)
        sgemm_kernel<true,false,true><<<dim3(D_/128, M_/128), 256>>>(
            ph, W2 + (size_t)l*FF_*D_, b2 + (size_t)l*D_, px, pt, M_, D_, FF_);
        float* ln2_dst = (l == L_-1) ? out : px;
        ln_kernel<<<M_, 256>>>(pt, ln2g + (size_t)l*D_, ln2b + (size_t)l*D_, ln2_dst);
    }
}

// round 6
// speedup vs baseline: 1.4943x; 1.4943x over previous
#include <cuda_runtime.h>
#include <cuda_bf16.h>
#include <math.h>
#include <stdint.h>

// Problem constants
#define B_  8
#define S_  1024
#define D_  512
#define H_  8
#define DH  64
#define FF_ 2048
#define L_  6
#define M_  (B_*S_)   // 8192 rows

// Transposed-weight layout (bf16 hi/lo), per layer:
#define OFF_QKV 0
#define OFF_FC  786432
#define OFF_W1  1048576
#define OFF_W2  2097152
#define WT_L    3145728
#define WT_TOT  (WT_L*L_)

// ---------------- scratch (static device globals; no allocation) ----------------
__device__ float g_x[M_*D_];                 // fp32 activations (residual stream)
__device__ float g_t[M_*D_];                 // pre-LN temp
__device__ float g_qkv[M_*3*D_];             // qkv fp32 (attention input)
__device__ unsigned short g_xh[M_*D_],  g_xl[M_*D_];    // x bf16 hi/lo
__device__ unsigned short g_ah[M_*D_],  g_al[M_*D_];    // attention out bf16 hi/lo
__device__ unsigned short g_hh[M_*FF_], g_hl[M_*FF_];   // ffn hidden bf16 hi/lo
__device__ unsigned short g_wth[WT_TOT], g_wtl[WT_TOT]; // transposed weights bf16 hi/lo
__device__ int g_pos[M_];

// ============================================================================
// helpers (baseline sm_80+ PTX only — no tcgen05 on this toolchain target)
// ============================================================================
__device__ __forceinline__ uint32_t su32(const void* p) {
    uint32_t a;
    asm("{ .reg .u64 t; cvta.to.shared.u64 t, %1; cvt.u32.u64 %0, t; }"
        : "=r"(a) : "l"(p));
    return a;
}

__device__ __forceinline__ void cp16(uint32_t s, const void* g) {
    asm volatile("cp.async.cg.shared.global [%0], [%1], 16;" :: "r"(s), "l"(g) : "memory");
}

__device__ __forceinline__ void ldsm4(uint32_t* r, uint32_t addr) {
    asm volatile("ldmatrix.sync.aligned.m8n8.x4.shared.b16 {%0,%1,%2,%3}, [%4];"
        : "=r"(r[0]), "=r"(r[1]), "=r"(r[2]), "=r"(r[3]) : "r"(addr));
}

__device__ __forceinline__ void mma_bf16(float* c, const uint32_t* a, const uint32_t* b) {
    asm volatile(
        "mma.sync.aligned.m16n8k16.row.col.f32.bf16.bf16.f32 "
        "{%0,%1,%2,%3}, {%4,%5,%6,%7}, {%8,%9}, {%0,%1,%2,%3};"
        : "+f"(c[0]), "+f"(c[1]), "+f"(c[2]), "+f"(c[3])
        : "r"(a[0]), "r"(a[1]), "r"(a[2]), "r"(a[3]), "r"(b[0]), "r"(b[1]));
}

// ============================================================================
// Position scan
// ============================================================================
__global__ void pos_scan_kernel(const int* __restrict__ mask)
{
    __shared__ int sc[S_];
    int b = blockIdx.x;
    int t = threadIdx.x;
    int v = (mask[b*S_ + t] != 0) ? 1 : 0;
    sc[t] = v;
    __syncthreads();
    for (int off = 1; off < S_; off <<= 1) {
        int add = (t >= off) ? sc[t - off] : 0;
        __syncthreads();
        sc[t] += add;
        __syncthreads();
    }
    g_pos[b*S_ + t] = v ? sc[t] : 0;
}

// ============================================================================
// x = x_in + sin_table[pos]; emit fp32 + bf16 hi/lo
// ============================================================================
__global__ void add_pos_kernel(const float* __restrict__ xin)
{
    int idx = blockIdx.x * 256 + threadIdx.x;
    int d = idx & (D_-1);
    int row = idx >> 9;
    int pos = g_pos[row];
    float e = 0.f;
    if (pos > 0) {
        const float c = -9.210340371976184f / 255.0f;
        if (d < 256) e = sinf((float)pos * expf((float)d * c));
        else         e = cosf((float)pos * expf((float)(d - 256) * c));
    }
    float v = xin[idx] + e;
    g_x[idx] = v;
    __nv_bfloat16 h = __float2bfloat16(v);
    g_xh[idx] = __bfloat16_as_ushort(h);
    g_xl[idx] = __bfloat16_as_ushort(__float2bfloat16(v - __bfloat162float(h)));
}

// ============================================================================
// Weight transpose + bf16 split: W[K,N] -> T_hi/T_lo [N,K]  (grid.z = layer)
// ============================================================================
__global__ void transpose_split_kernel(const float* __restrict__ W,
                                       unsigned short* __restrict__ Th,
                                       unsigned short* __restrict__ Tl,
                                       int K, int N, size_t out_off)
{
    __shared__ float t[32][33];
    int l = blockIdx.z;
    const float* Wp = W + (size_t)l * K * N;
    unsigned short* Thp = Th + (size_t)l * WT_L + out_off;
    unsigned short* Tlp = Tl + (size_t)l * WT_L + out_off;
    int n0 = blockIdx.x * 32, k0 = blockIdx.y * 32;
    int tx = threadIdx.x, ty = threadIdx.y;   // 32 x 8
    #pragma unroll
    for (int i = 0; i < 4; i++)
        t[ty + 8*i][tx] = Wp[(size_t)(k0 + ty + 8*i) * N + n0 + tx];
    __syncthreads();
    #pragma unroll
    for (int i = 0; i < 4; i++) {
        float v = t[tx][ty + 8*i];
        size_t o = (size_t)(n0 + ty + 8*i) * K + k0 + tx;
        __nv_bfloat16 h = __float2bfloat16(v);
        Thp[o] = __bfloat16_as_ushort(h);
        Tlp[o] = __bfloat16_as_ushort(__float2bfloat16(v - __bfloat162float(h)));
    }
}

// ============================================================================
// mma.sync bf16 GEMM: C[M,N] = A[M,K] @ B^T (B given as [N,K] bf16 hi/lo rows)
// 3-term split AhBh + AhBl + AlBh, fp32 accum.
// CTA 128x128, BK=32, 256 thr, 8 warps (2x4) of 64x32, cp.async double buffer.
// EPI: 0 = fp32 out; 1 = +bias +Res fp32 out; 2 = relu(+bias) -> bf16 hi/lo
// ============================================================================
#define BK 32
#define ROW_B 80            // smem row stride bytes (40 bf16, conflict-free)
#define TEN_B 10240         // 128 rows * 80B
#define STG_B (4*TEN_B)     // 4 tensors per stage

template<int EPI>
__global__ void __launch_bounds__(256)
gemm_mma(const unsigned short* __restrict__ Ah, const unsigned short* __restrict__ Al,
         const unsigned short* __restrict__ Bh, const unsigned short* __restrict__ Bl,
         const float* __restrict__ bias, const float* __restrict__ Res,
         float* __restrict__ Cf,
         unsigned short* __restrict__ Ch, unsigned short* __restrict__ Cl,
         int N, int K)
{
    extern __shared__ __align__(16) char smem[];
    const uint32_t sb = su32(smem);
    const int tid = threadIdx.x;
    const int lane = tid & 31, wid = tid >> 5;
    const int wm = wid & 1, wn = wid >> 1;
    const int m0 = blockIdx.y * 128, n0 = blockIdx.x * 128;

    float acc[4][4][4];
    #pragma unroll
    for (int i = 0; i < 4; i++)
        #pragma unroll
        for (int j = 0; j < 4; j++)
            #pragma unroll
            for (int k = 0; k < 4; k++) acc[i][j][k] = 0.f;

    const int nc = K / BK;

    // ---- chunk loader (8 cp.async of 16B per thread) ----
    auto load_chunk = [&](int c, int stage) {
        const uint32_t st = sb + stage * STG_B;
        const int k0 = c * BK;
        #pragma unroll
        for (int j = 0; j < 2; j++) {
            int idx = tid * 2 + j;          // 0..511
            int r = idx >> 2, sg = idx & 3;
            uint32_t so = r * ROW_B + sg * 16;
            const size_t ga = (size_t)(m0 + r) * K + k0 + sg * 8;
            const size_t gb = (size_t)(n0 + r) * K + k0 + sg * 8;
            cp16(st +           so, Ah + ga);
            cp16(st +   TEN_B + so, Al + ga);
            cp16(st + 2*TEN_B + so, Bh + gb);
            cp16(st + 3*TEN_B + so, Bl + gb);
        }
        asm volatile("cp.async.commit_group;" ::: "memory");
    };

    // ---- chunk compute ----
    auto compute_chunk = [&](int stage) {
        const uint32_t st = sb + stage * STG_B;
        const uint32_t lrow = (lane & 15);
        const uint32_t lcol = (lane >> 4) * 16;    // byte offset (8 bf16)
        #pragma unroll
        for (int ks = 0; ks < 2; ks++) {
            const uint32_t kb = ks * 32 + lcol;    // k16 step = 32B
            uint32_t aH[4][4], aL[4][4], bH[4][2], bL[4][2];
            #pragma unroll
            for (int mt = 0; mt < 4; mt++) {
                uint32_t ad = st + (wm*64 + mt*16 + lrow) * ROW_B + kb;
                ldsm4(aH[mt], ad);
                ldsm4(aL[mt], ad + TEN_B);
            }
            #pragma unroll
            for (int g = 0; g < 2; g++) {
                uint32_t bd = st + 2*TEN_B + (wn*32 + g*16 + lrow) * ROW_B + kb;
                uint32_t t0[4], t1[4];
                ldsm4(t0, bd);
                ldsm4(t1, bd + TEN_B);
                bH[g*2][0] = t0[0]; bH[g*2][1] = t0[2];
                bH[g*2+1][0] = t0[1]; bH[g*2+1][1] = t0[3];
                bL[g*2][0] = t1[0]; bL[g*2][1] = t1[2];
                bL[g*2+1][0] = t1[1]; bL[g*2+1][1] = t1[3];
            }
            #pragma unroll
            for (int mt = 0; mt < 4; mt++)
                #pragma unroll
                for (int nt = 0; nt < 4; nt++) {
                    mma_bf16(acc[mt][nt], aH[mt], bH[nt]);
                    mma_bf16(acc[mt][nt], aH[mt], bL[nt]);
                    mma_bf16(acc[mt][nt], aL[mt], bH[nt]);
                }
        }
    };

    load_chunk(0, 0);
    for (int c = 0; c < nc; c++) {
        if (c + 1 < nc) {
            load_chunk(c + 1, (c + 1) & 1);
            asm volatile("cp.async.wait_group 1;" ::: "memory");
        } else {
            asm volatile("cp.async.wait_group 0;" ::: "memory");
        }
        __syncthreads();
        compute_chunk(c & 1);
        __syncthreads();
    }

    // ---- epilogue ----
    const int r0 = lane >> 2;
    const int cp = (lane & 3) * 2;
    #pragma unroll
    for (int mt = 0; mt < 4; mt++) {
        #pragma unroll
        for (int half = 0; half < 2; half++) {
            const size_t row = (size_t)(m0 + wm*64 + mt*16 + half*8 + r0);
            #pragma unroll
            for (int nt = 0; nt < 4; nt++) {
                const int col = n0 + wn*32 + nt*8 + cp;
                float v0 = acc[mt][nt][half*2 + 0];
                float v1 = acc[mt][nt][half*2 + 1];
                if (EPI == 0) {
                    float2 o; o.x = v0; o.y = v1;
                    *(float2*)&Cf[row*N + col] = o;
                } else if (EPI == 1) {
                    float2 bb = *(const float2*)&bias[col];
                    float2 rr = *(const float2*)&Res[row*N + col];
                    float2 o; o.x = v0 + bb.x + rr.x; o.y = v1 + bb.y + rr.y;
                    *(float2*)&Cf[row*N + col] = o;
                } else {
                    float2 bb = *(const float2*)&bias[col];
                    v0 = fmaxf(v0 + bb.x, 0.f);
                    v1 = fmaxf(v1 + bb.y, 0.f);
                    __nv_bfloat16 h0 = __float2bfloat16(v0);
                    __nv_bfloat16 h1 = __float2bfloat16(v1);
                    ushort2 hh, ll;
                    hh.x = __bfloat16_as_ushort(h0);
                    hh.y = __bfloat16_as_ushort(h1);
                    ll.x = __bfloat16_as_ushort(__float2bfloat16(v0 - __bfloat162float(h0)));
                    ll.y = __bfloat16_as_ushort(__float2bfloat16(v1 - __bfloat162float(h1)));
                    *(ushort2*)&Ch[row*N + col] = hh;
                    *(ushort2*)&Cl[row*N + col] = ll;
                }
            }
        }
    }
}

// ============================================================================
// Flash attention (fp32 SIMT): outputs bf16 hi/lo
// ============================================================================
#define KQ_LD 68

__global__ void __launch_bounds__(256)
attn_kernel(const float* __restrict__ qkv, const int* __restrict__ mask,
            unsigned short* __restrict__ out_h, unsigned short* __restrict__ out_l)
{
    extern __shared__ float sm[];
    float* QsT = sm;
    float* KsT = QsT + 64*KQ_LD;
    float* Vs  = KsT + 64*KQ_LD;
    float* Ps  = Vs  + 64*64;
    float* m_s = Ps  + 64*64;
    float* l_s = m_s + 64;
    float* c_s = l_s + 64;
    int*   kvm = (int*)(c_s + 64);

    const int tid = threadIdx.x;
    const int tx = tid & 15, ty = tid >> 4;
    const int q0 = blockIdx.x * 64;
    const int b  = blockIdx.y >> 3;
    const int h  = blockIdx.y & 7;
    const int RS = 3 * D_;

    const float* qbase  = qkv + ((size_t)(b*S_ + q0))*RS + h*DH;
    const float* kbase0 = qkv + ((size_t)b*S_)*RS + D_   + h*DH;
    const float* vbase0 = qkv + ((size_t)b*S_)*RS + 2*D_ + h*DH;

    #pragma unroll
    for (int i = 0; i < 16; i++) {
        int idx = i*256 + tid;
        int r = idx >> 6, d = idx & 63;
        QsT[d*KQ_LD + r] = qbase[(size_t)r*RS + d];
    }
    if (tid < 64) { m_s[tid] = -INFINITY; l_s[tid] = 0.f; }

    float o[4][4];
    #pragma unroll
    for (int ii = 0; ii < 4; ii++)
        #pragma unroll
        for (int jj = 0; jj < 4; jj++) o[ii][jj] = 0.f;

    for (int j = 0; j < S_/64; j++) {
        __syncthreads();
        const float* kb = kbase0 + (size_t)(j*64)*RS;
        const float* vb = vbase0 + (size_t)(j*64)*RS;
        #pragma unroll
        for (int i = 0; i < 16; i++) {
            int idx = i*256 + tid;
            int r = idx >> 6, d = idx & 63;
            KsT[d*KQ_LD + r] = kb[(size_t)r*RS + d];
            Vs[r*64 + d]     = vb[(size_t)r*RS + d];
        }
        if (tid < 64) kvm[tid] = mask[b*S_ + j*64 + tid];
        __syncthreads();

        float s[4][4];
        #pragma unroll
        for (int ii = 0; ii < 4; ii++)
            #pragma unroll
            for (int jj = 0; jj < 4; jj++) s[ii][jj] = 0.f;
        #pragma unroll
        for (int k = 0; k < 64; k++) {
            float4 a = *(const float4*)&KsT[k*KQ_LD + ty*4];
            float4 q = *(const float4*)&QsT[k*KQ_LD + tx*4];
            float ar[4] = {a.x,a.y,a.z,a.w};
            float qr[4] = {q.x,q.y,q.z,q.w};
            #pragma unroll
            for (int ii = 0; ii < 4; ii++)
                #pragma unroll
                for (int jj = 0; jj < 4; jj++)
                    s[ii][jj] += ar[ii] * qr[jj];
        }
        #pragma unroll
        for (int ii = 0; ii < 4; ii++) {
            if (kvm[ty*4 + ii] == 0) {
                s[ii][0] = -INFINITY; s[ii][1] = -INFINITY;
                s[ii][2] = -INFINITY; s[ii][3] = -INFINITY;
            }
            float4 w; w.x=s[ii][0]; w.y=s[ii][1]; w.z=s[ii][2]; w.w=s[ii][3];
            *(float4*)&Ps[(ty*4+ii)*64 + tx*4] = w;
        }
        __syncthreads();

        if (tid < 64) {
            int r = tid;
            float mo = m_s[r];
            float tmx = -INFINITY;
            #pragma unroll 8
            for (int kv = 0; kv < 64; kv++) tmx = fmaxf(tmx, Ps[kv*64 + r]);
            float mn = fmaxf(mo, tmx);
            float c, sum = 0.f;
            if (mn == -INFINITY) {
                c = 1.f;
                #pragma unroll 8
                for (int kv = 0; kv < 64; kv++) Ps[kv*64 + r] = 0.f;
            } else {
                c = __expf(mo - mn);
                #pragma unroll 8
                for (int kv = 0; kv < 64; kv++) {
                    float p = __expf(Ps[kv*64 + r] - mn);
                    Ps[kv*64 + r] = p;
                    sum += p;
                }
            }
            l_s[r] = l_s[r]*c + sum;
            m_s[r] = mn;
            c_s[r] = c;
        }
        __syncthreads();

        float cr[4];
        #pragma unroll
        for (int ii = 0; ii < 4; ii++) cr[ii] = c_s[ty*4 + ii];
        #pragma unroll
        for (int ii = 0; ii < 4; ii++)
            #pragma unroll
            for (int jj = 0; jj < 4; jj++) o[ii][jj] *= cr[ii];
        #pragma unroll
        for (int k = 0; k < 64; k++) {
            float4 p = *(const float4*)&Ps[k*64 + ty*4];
            float4 v = *(const float4*)&Vs[k*64 + tx*4];
            float pr[4] = {p.x,p.y,p.z,p.w};
            float vr[4] = {v.x,v.y,v.z,v.w};
            #pragma unroll
            for (int ii = 0; ii < 4; ii++)
                #pragma unroll
                for (int jj = 0; jj < 4; jj++)
                    o[ii][jj] += pr[ii] * vr[jj];
        }
    }

    float inv[4];
    #pragma unroll
    for (int ii = 0; ii < 4; ii++) inv[ii] = 1.f / l_s[ty*4 + ii];
    #pragma unroll
    for (int ii = 0; ii < 4; ii++) {
        size_t base = ((size_t)(b*S_ + q0 + ty*4 + ii))*D_ + h*DH + tx*4;
        float w0 = o[ii][0]*inv[ii], w1 = o[ii][1]*inv[ii];
        float w2 = o[ii][2]*inv[ii], w3 = o[ii][3]*inv[ii];
        __nv_bfloat16 h0 = __float2bfloat16(w0), h1 = __float2bfloat16(w1);
        __nv_bfloat16 h2 = __float2bfloat16(w2), h3 = __float2bfloat16(w3);
        ushort4 hh, ll;
        hh.x = __bfloat16_as_ushort(h0); hh.y = __bfloat16_as_ushort(h1);
        hh.z = __bfloat16_as_ushort(h2); hh.w = __bfloat16_as_ushort(h3);
        ll.x = __bfloat16_as_ushort(__float2bfloat16(w0 - __bfloat162float(h0)));
        ll.y = __bfloat16_as_ushort(__float2bfloat16(w1 - __bfloat162float(h1)));
        ll.z = __bfloat16_as_ushort(__float2bfloat16(w2 - __bfloat162float(h2)));
        ll.w = __bfloat16_as_ushort(__float2bfloat16(w3 - __bfloat162float(h3)));
        *(ushort4*)&out_h[base] = hh;
        *(ushort4*)&out_l[base] = ll;
    }
}

// ============================================================================
// LayerNorm over last dim (512); optional bf16 hi/lo side outputs
// ============================================================================
template<bool SPLIT>
__global__ void __launch_bounds__(256)
ln_kernel(const float* __restrict__ X, const float* __restrict__ g,
          const float* __restrict__ bta, float* __restrict__ Y,
          unsigned short* __restrict__ Yh, unsigned short* __restrict__ Yl)
{
    __shared__ float red[32];
    const int row = blockIdx.x;
    const int t = threadIdx.x;
    const int lane = t & 31, w = t >> 5;

    float2 v = ((const float2*)(X + (size_t)row*D_))[t];

    float s = v.x + v.y;
    #pragma unroll
    for (int o = 16; o; o >>= 1) s += __shfl_xor_sync(0xffffffffu, s, o);
    if (lane == 0) red[w] = s;
    __syncthreads();
    if (t < 32) {
        float a = (t < 8) ? red[t] : 0.f;
        #pragma unroll
        for (int o = 4; o; o >>= 1) a += __shfl_xor_sync(0xffffffffu, a, o);
        if (t == 0) red[0] = a;
    }
    __syncthreads();
    const float mu = red[0] * (1.f / D_);
    __syncthreads();

    float d0 = v.x - mu, d1 = v.y - mu;
    float q = d0*d0 + d1*d1;
    #pragma unroll
    for (int o = 16; o; o >>= 1) q += __shfl_xor_sync(0xffffffffu, q, o);
    if (lane == 0) red[w] = q;
    __syncthreads();
    if (t < 32) {
        float a = (t < 8) ? red[t] : 0.f;
        #pragma unroll
        for (int o = 4; o; o >>= 1) a += __shfl_xor_sync(0xffffffffu, a, o);
        if (t == 0) red[0] = a;
    }
    __syncthreads();
    const float var = red[0] * (1.f / D_);
    const float inv = rsqrtf(var + 1e-5f);

    float2 gv = ((const float2*)g)[t];
    float2 bv = ((const float2*)bta)[t];
    float y0 = d0 * inv * gv.x + bv.x;
    float y1 = d1 * inv * gv.y + bv.y;
    float2 o2; o2.x = y0; o2.y = y1;
    ((float2*)(Y + (size_t)row*D_))[t] = o2;
    if (SPLIT) {
        __nv_bfloat16 h0 = __float2bfloat16(y0), h1 = __float2bfloat16(y1);
        ushort2 hh, ll;
        hh.x = __bfloat16_as_ushort(h0); hh.y = __bfloat16_as_ushort(h1);
        ll.x = __bfloat16_as_ushort(__float2bfloat16(y0 - __bfloat162float(h0)));
        ll.y = __bfloat16_as_ushort(__float2bfloat16(y1 - __bfloat162float(h1)));
        ((ushort2*)(Yh + (size_t)row*D_))[t] = hh;
        ((ushort2*)(Yl + (size_t)row*D_))[t] = ll;
    }
}

// ============================================================================
// Host launcher
// ============================================================================
extern "C" void kernel_launch(void* const* d_in, const int* in_sizes, int n_in,
                              void* d_out, int out_size)
{
    const float* x_in  = (const float*)d_in[0];
    const int*   mask  = (const int*)d_in[3];
    const float* Wqkv  = (const float*)d_in[4];
    const float* Wfc   = (const float*)d_in[5];
    const float* bfc   = (const float*)d_in[6];
    const float* ln1g  = (const float*)d_in[7];
    const float* ln1b  = (const float*)d_in[8];
    const float* ln2g  = (const float*)d_in[9];
    const float* ln2b  = (const float*)d_in[10];
    const float* W1    = (const float*)d_in[11];
    const float* b1    = (const float*)d_in[12];
    const float* W2    = (const float*)d_in[13];
    const float* b2    = (const float*)d_in[14];
    float* out = (float*)d_out;

    float *px, *pt, *pqkv;
    unsigned short *pxh, *pxl, *pah, *pal, *phh, *phl, *pwh, *pwl;
    cudaGetSymbolAddress((void**)&px,   g_x);
    cudaGetSymbolAddress((void**)&pt,   g_t);
    cudaGetSymbolAddress((void**)&pqkv, g_qkv);
    cudaGetSymbolAddress((void**)&pxh,  g_xh);
    cudaGetSymbolAddress((void**)&pxl,  g_xl);
    cudaGetSymbolAddress((void**)&pah,  g_ah);
    cudaGetSymbolAddress((void**)&pal,  g_al);
    cudaGetSymbolAddress((void**)&phh,  g_hh);
    cudaGetSymbolAddress((void**)&phl,  g_hl);
    cudaGetSymbolAddress((void**)&pwh,  g_wth);
    cudaGetSymbolAddress((void**)&pwl,  g_wtl);

    const int GSM = 2 * STG_B;   // 80 KB
    cudaFuncSetAttribute(gemm_mma<0>, cudaFuncAttributeMaxDynamicSharedMemorySize, GSM);
    cudaFuncSetAttribute(gemm_mma<1>, cudaFuncAttributeMaxDynamicSharedMemorySize, GSM);
    cudaFuncSetAttribute(gemm_mma<2>, cudaFuncAttributeMaxDynamicSharedMemorySize, GSM);

    const size_t attn_smem = (size_t)(64*KQ_LD*2 + 64*64*2 + 64*3) * sizeof(float)
                           + 64 * sizeof(int);
    cudaFuncSetAttribute(attn_kernel, cudaFuncAttributeMaxDynamicSharedMemorySize,
                         (int)attn_smem);

    // weight transpose + bf16 split (all layers)
    transpose_split_kernel<<<dim3(1536/32, 512/32, L_), dim3(32,8)>>>(Wqkv, pwh, pwl, 512, 1536, OFF_QKV);
    transpose_split_kernel<<<dim3( 512/32, 512/32, L_), dim3(32,8)>>>(Wfc,  pwh, pwl, 512,  512, OFF_FC);
    transpose_split_kernel<<<dim3(2048/32, 512/32, L_), dim3(32,8)>>>(W1,   pwh, pwl, 512, 2048, OFF_W1);
    transpose_split_kernel<<<dim3( 512/32,2048/32, L_), dim3(32,8)>>>(W2,   pwh, pwl, 2048, 512, OFF_W2);

    // position embedding
    pos_scan_kernel<<<B_, S_>>>(mask);
    add_pos_kernel<<<(M_*D_)/256, 256>>>(x_in);

    for (int l = 0; l < L_; l++) {
        const unsigned short* wqh = pwh + (size_t)l*WT_L + OFF_QKV;
        const unsigned short* wql = pwl + (size_t)l*WT_L + OFF_QKV;
        const unsigned short* wfh = pwh + (size_t)l*WT_L + OFF_FC;
        const unsigned short* wfl = pwl + (size_t)l*WT_L + OFF_FC;
        const unsigned short* w1h = pwh + (size_t)l*WT_L + OFF_W1;
        const unsigned short* w1l = pwl + (size_t)l*WT_L + OFF_W1;
        const unsigned short* w2h = pwh + (size_t)l*WT_L + OFF_W2;
        const unsigned short* w2l = pwl + (size_t)l*WT_L + OFF_W2;

        // qkv = x @ Wqkv  [8192,512]x[512,1536] -> fp32
        gemm_mma<0><<<dim3(12, 64), 256, GSM>>>(pxh, pxl, wqh, wql,
            nullptr, nullptr, pqkv, nullptr, nullptr, 3*D_, D_);

        // attention -> att bf16 hi/lo
        attn_kernel<<<dim3(S_/64, B_*H_), 256, attn_smem>>>(pqkv, mask, pah, pal);

        // o @ Wfc + bfc + residual(x) -> t ; LN1 -> x (+hi/lo)
        gemm_mma<1><<<dim3(4, 64), 256, GSM>>>(pah, pal, wfh, wfl,
            bfc + (size_t)l*D_, px, pt, nullptr, nullptr, D_, D_);
        ln_kernel<true><<<M_, 256>>>(pt, ln1g + (size_t)l*D_, ln1b + (size_t)l*D_,
                                     px, pxh, pxl);

        // h = relu(x @ W1 + b1) -> bf16 hi/lo
        gemm_mma<2><<<dim3(16, 64), 256, GSM>>>(pxh, pxl, w1h, w1l,
            b1 + (size_t)l*FF_, nullptr, nullptr, phh, phl, FF_, D_);

        // h @ W2 + b2 + residual(x) -> t ; LN2 -> x (+hi/lo) or d_out
        gemm_mma<1><<<dim3(4, 64), 256, GSM>>>(phh, phl, w2h, w2l,
            b2 + (size_t)l*D_, px, pt, nullptr, nullptr, D_, FF_);
        if (l == L_-1)
            ln_kernel<false><<<M_, 256>>>(pt, ln2g + (size_t)l*D_, ln2b + (size_t)l*D_,
                                          out, nullptr, nullptr);
        else
            ln_kernel<true><<<M_, 256>>>(pt, ln2g + (size_t)l*D_, ln2b + (size_t)l*D_,
                                         px, pxh, pxl);
    }
}

// round 7
// speedup vs baseline: 1.8441x; 1.2341x over previous
#include <cuda_runtime.h>
#include <cuda_bf16.h>
#include <math.h>
#include <stdint.h>

// Problem constants
#define B_  8
#define S_  1024
#define D_  512
#define H_  8
#define DH  64
#define FF_ 2048
#define L_  6
#define M_  (B_*S_)   // 8192 rows

// Transposed-weight layout (bf16 hi/lo), per layer:
#define OFF_QKV 0
#define OFF_FC  786432
#define OFF_W1  1048576
#define OFF_W2  2097152
#define WT_L    3145728
#define WT_TOT  (WT_L*L_)

// ---------------- scratch (static device globals; no allocation) ----------------
__device__ float g_x[M_*D_];                 // fp32 activations (residual stream)
__device__ float g_t[M_*D_];                 // pre-LN temp
__device__ unsigned short g_qh[M_*3*D_], g_ql[M_*3*D_]; // qkv bf16 hi/lo
__device__ unsigned short g_xh[M_*D_],  g_xl[M_*D_];    // x bf16 hi/lo
__device__ unsigned short g_ah[M_*D_],  g_al[M_*D_];    // attention out bf16 hi/lo
__device__ unsigned short g_hh[M_*FF_], g_hl[M_*FF_];   // ffn hidden bf16 hi/lo
__device__ unsigned short g_wth[WT_TOT], g_wtl[WT_TOT]; // transposed weights bf16 hi/lo
__device__ int g_pos[M_];

// ============================================================================
// helpers (baseline sm_80+ PTX only — no tcgen05 on this toolchain target)
// ============================================================================
__device__ __forceinline__ uint32_t su32(const void* p) {
    uint32_t a;
    asm("{ .reg .u64 t; cvta.to.shared.u64 t, %1; cvt.u32.u64 %0, t; }"
        : "=r"(a) : "l"(p));
    return a;
}

__device__ __forceinline__ void cp16(uint32_t s, const void* g) {
    asm volatile("cp.async.cg.shared.global [%0], [%1], 16;" :: "r"(s), "l"(g) : "memory");
}

__device__ __forceinline__ void ldsm4(uint32_t* r, uint32_t addr) {
    asm volatile("ldmatrix.sync.aligned.m8n8.x4.shared.b16 {%0,%1,%2,%3}, [%4];"
        : "=r"(r[0]), "=r"(r[1]), "=r"(r[2]), "=r"(r[3]) : "r"(addr));
}

__device__ __forceinline__ void ldsm4t(uint32_t* r, uint32_t addr) {
    asm volatile("ldmatrix.sync.aligned.m8n8.x4.trans.shared.b16 {%0,%1,%2,%3}, [%4];"
        : "=r"(r[0]), "=r"(r[1]), "=r"(r[2]), "=r"(r[3]) : "r"(addr));
}

__device__ __forceinline__ void mma_bf16(float* c, const uint32_t* a, const uint32_t* b) {
    asm volatile(
        "mma.sync.aligned.m16n8k16.row.col.f32.bf16.bf16.f32 "
        "{%0,%1,%2,%3}, {%4,%5,%6,%7}, {%8,%9}, {%0,%1,%2,%3};"
        : "+f"(c[0]), "+f"(c[1]), "+f"(c[2]), "+f"(c[3])
        : "r"(a[0]), "r"(a[1]), "r"(a[2]), "r"(a[3]), "r"(b[0]), "r"(b[1]));
}

__device__ __forceinline__ void bf16_split(float v, unsigned short& hi, unsigned short& lo) {
    __nv_bfloat16 h = __float2bfloat16(v);
    hi = __bfloat16_as_ushort(h);
    lo = __bfloat16_as_ushort(__float2bfloat16(v - __bfloat162float(h)));
}

// ============================================================================
// Position scan
// ============================================================================
__global__ void pos_scan_kernel(const int* __restrict__ mask)
{
    __shared__ int sc[S_];
    int b = blockIdx.x;
    int t = threadIdx.x;
    int v = (mask[b*S_ + t] != 0) ? 1 : 0;
    sc[t] = v;
    __syncthreads();
    for (int off = 1; off < S_; off <<= 1) {
        int add = (t >= off) ? sc[t - off] : 0;
        __syncthreads();
        sc[t] += add;
        __syncthreads();
    }
    g_pos[b*S_ + t] = v ? sc[t] : 0;
}

// ============================================================================
// x = x_in + sin_table[pos]; emit fp32 + bf16 hi/lo
// ============================================================================
__global__ void add_pos_kernel(const float* __restrict__ xin)
{
    int idx = blockIdx.x * 256 + threadIdx.x;
    int d = idx & (D_-1);
    int row = idx >> 9;
    int pos = g_pos[row];
    float e = 0.f;
    if (pos > 0) {
        const float c = -9.210340371976184f / 255.0f;
        if (d < 256) e = sinf((float)pos * expf((float)d * c));
        else         e = cosf((float)pos * expf((float)(d - 256) * c));
    }
    float v = xin[idx] + e;
    g_x[idx] = v;
    bf16_split(v, g_xh[idx], g_xl[idx]);
}

// ============================================================================
// Weight transpose + bf16 split: W[K,N] -> T_hi/T_lo [N,K]  (grid.z = layer)
// ============================================================================
__global__ void transpose_split_kernel(const float* __restrict__ W,
                                       unsigned short* __restrict__ Th,
                                       unsigned short* __restrict__ Tl,
                                       int K, int N, size_t out_off)
{
    __shared__ float t[32][33];
    int l = blockIdx.z;
    const float* Wp = W + (size_t)l * K * N;
    unsigned short* Thp = Th + (size_t)l * WT_L + out_off;
    unsigned short* Tlp = Tl + (size_t)l * WT_L + out_off;
    int n0 = blockIdx.x * 32, k0 = blockIdx.y * 32;
    int tx = threadIdx.x, ty = threadIdx.y;   // 32 x 8
    #pragma unroll
    for (int i = 0; i < 4; i++)
        t[ty + 8*i][tx] = Wp[(size_t)(k0 + ty + 8*i) * N + n0 + tx];
    __syncthreads();
    #pragma unroll
    for (int i = 0; i < 4; i++) {
        float v = t[tx][ty + 8*i];
        size_t o = (size_t)(n0 + ty + 8*i) * K + k0 + tx;
        bf16_split(v, Thp[o], Tlp[o]);
    }
}

// ============================================================================
// mma.sync bf16 GEMM: C[M,N] = A[M,K] @ B^T (B given as [N,K] bf16 hi/lo rows)
// 3-term split AhBh + AhBl + AlBh, fp32 accum.
// CTA 128x128, BK=32, 256 thr, 8 warps (2x4) of 64x32, cp.async double buffer.
// EPI: 0 = fp32 out; 1 = +bias +Res fp32 out; 2 = relu(+bias) -> bf16 hi/lo;
//      3 = plain -> bf16 hi/lo
// ============================================================================
#define BK 32
#define ROW_B 80            // smem row stride bytes (40 bf16, conflict-free)
#define TEN_B 10240         // 128 rows * 80B
#define STG_B (4*TEN_B)     // 4 tensors per stage

template<int EPI>
__global__ void __launch_bounds__(256)
gemm_mma(const unsigned short* __restrict__ Ah, const unsigned short* __restrict__ Al,
         const unsigned short* __restrict__ Bh, const unsigned short* __restrict__ Bl,
         const float* __restrict__ bias, const float* __restrict__ Res,
         float* __restrict__ Cf,
         unsigned short* __restrict__ Ch, unsigned short* __restrict__ Cl,
         int N, int K)
{
    extern __shared__ __align__(16) char smem[];
    const uint32_t sb = su32(smem);
    const int tid = threadIdx.x;
    const int lane = tid & 31, wid = tid >> 5;
    const int wm = wid & 1, wn = wid >> 1;
    const int m0 = blockIdx.y * 128, n0 = blockIdx.x * 128;

    float acc[4][4][4];
    #pragma unroll
    for (int i = 0; i < 4; i++)
        #pragma unroll
        for (int j = 0; j < 4; j++)
            #pragma unroll
            for (int k = 0; k < 4; k++) acc[i][j][k] = 0.f;

    const int nc = K / BK;

    auto load_chunk = [&](int c, int stage) {
        const uint32_t st = sb + stage * STG_B;
        const int k0 = c * BK;
        #pragma unroll
        for (int j = 0; j < 2; j++) {
            int idx = tid * 2 + j;          // 0..511
            int r = idx >> 2, sg = idx & 3;
            uint32_t so = r * ROW_B + sg * 16;
            const size_t ga = (size_t)(m0 + r) * K + k0 + sg * 8;
            const size_t gb = (size_t)(n0 + r) * K + k0 + sg * 8;
            cp16(st +           so, Ah + ga);
            cp16(st +   TEN_B + so, Al + ga);
            cp16(st + 2*TEN_B + so, Bh + gb);
            cp16(st + 3*TEN_B + so, Bl + gb);
        }
        asm volatile("cp.async.commit_group;" ::: "memory");
    };

    auto compute_chunk = [&](int stage) {
        const uint32_t st = sb + stage * STG_B;
        const uint32_t lrow = (lane & 15);
        const uint32_t lcol = (lane >> 4) * 16;
        #pragma unroll
        for (int ks = 0; ks < 2; ks++) {
            const uint32_t kb = ks * 32 + lcol;
            uint32_t aH[4][4], aL[4][4], bH[4][2], bL[4][2];
            #pragma unroll
            for (int mt = 0; mt < 4; mt++) {
                uint32_t ad = st + (wm*64 + mt*16 + lrow) * ROW_B + kb;
                ldsm4(aH[mt], ad);
                ldsm4(aL[mt], ad + TEN_B);
            }
            #pragma unroll
            for (int g = 0; g < 2; g++) {
                uint32_t bd = st + 2*TEN_B + (wn*32 + g*16 + lrow) * ROW_B + kb;
                uint32_t t0[4], t1[4];
                ldsm4(t0, bd);
                ldsm4(t1, bd + TEN_B);
                bH[g*2][0] = t0[0]; bH[g*2][1] = t0[2];
                bH[g*2+1][0] = t0[1]; bH[g*2+1][1] = t0[3];
                bL[g*2][0] = t1[0]; bL[g*2][1] = t1[2];
                bL[g*2+1][0] = t1[1]; bL[g*2+1][1] = t1[3];
            }
            #pragma unroll
            for (int mt = 0; mt < 4; mt++)
                #pragma unroll
                for (int nt = 0; nt < 4; nt++) {
                    mma_bf16(acc[mt][nt], aH[mt], bH[nt]);
                    mma_bf16(acc[mt][nt], aH[mt], bL[nt]);
                    mma_bf16(acc[mt][nt], aL[mt], bH[nt]);
                }
        }
    };

    load_chunk(0, 0);
    for (int c = 0; c < nc; c++) {
        if (c + 1 < nc) {
            load_chunk(c + 1, (c + 1) & 1);
            asm volatile("cp.async.wait_group 1;" ::: "memory");
        } else {
            asm volatile("cp.async.wait_group 0;" ::: "memory");
        }
        __syncthreads();
        compute_chunk(c & 1);
        __syncthreads();
    }

    // ---- epilogue ----
    const int r0 = lane >> 2;
    const int cp = (lane & 3) * 2;
    #pragma unroll
    for (int mt = 0; mt < 4; mt++) {
        #pragma unroll
        for (int half = 0; half < 2; half++) {
            const size_t row = (size_t)(m0 + wm*64 + mt*16 + half*8 + r0);
            #pragma unroll
            for (int nt = 0; nt < 4; nt++) {
                const int col = n0 + wn*32 + nt*8 + cp;
                float v0 = acc[mt][nt][half*2 + 0];
                float v1 = acc[mt][nt][half*2 + 1];
                if (EPI == 0) {
                    float2 o; o.x = v0; o.y = v1;
                    *(float2*)&Cf[row*N + col] = o;
                } else if (EPI == 1) {
                    float2 bb = *(const float2*)&bias[col];
                    float2 rr = *(const float2*)&Res[row*N + col];
                    float2 o; o.x = v0 + bb.x + rr.x; o.y = v1 + bb.y + rr.y;
                    *(float2*)&Cf[row*N + col] = o;
                } else {
                    if (EPI == 2) {
                        float2 bb = *(const float2*)&bias[col];
                        v0 = fmaxf(v0 + bb.x, 0.f);
                        v1 = fmaxf(v1 + bb.y, 0.f);
                    }
                    ushort2 hh, ll;
                    bf16_split(v0, hh.x, ll.x);
                    bf16_split(v1, hh.y, ll.y);
                    *(ushort2*)&Ch[row*N + col] = hh;
                    *(ushort2*)&Cl[row*N + col] = ll;
                }
            }
        }
    }
}

// ============================================================================
// Flash attention via mma.sync bf16 (hi/lo split, 3-term): scale = 1
// CTA: 128 q-rows x full S keys (64-key tiles). 256 thr, warps 4(m) x 2(n).
// Reads qkv bf16 hi/lo [row][1536]; writes attention out bf16 hi/lo [row][512].
// ============================================================================
#define AST 144                 // smem row stride bytes (64 bf16 + 16B pad)
#define A_QH 0
#define A_QL 18432
#define A_KH 36864              // + stage*9216
#define A_KL 55296
#define A_VH 73728
#define A_VL 92160
#define A_PH 110592
#define A_PL 129024
#define A_PM 147456             // float[2][128]
#define A_PS 148480             // float[2][128]
#define A_MS 149504             // float[128]
#define A_LS 150016             // float[128]
#define A_KM 150528             // int[2][64]
#define A_TOT 151552

__global__ void __launch_bounds__(256)
attn_mma(const unsigned short* __restrict__ qh, const unsigned short* __restrict__ ql,
         const int* __restrict__ mask,
         unsigned short* __restrict__ outh, unsigned short* __restrict__ outl)
{
    extern __shared__ __align__(16) char asmem[];
    const uint32_t sb = su32(asmem);
    float* pm  = (float*)(asmem + A_PM);
    float* ps  = (float*)(asmem + A_PS);
    float* m_s = (float*)(asmem + A_MS);
    float* l_s = (float*)(asmem + A_LS);
    int*   kvm = (int*)  (asmem + A_KM);

    const int tid = threadIdx.x, lane = tid & 31, wid = tid >> 5;
    const int wm = wid & 3, wn = wid >> 2;
    const int q0 = blockIdx.x * 128;
    const int b  = blockIdx.y >> 3;
    const int h  = blockIdx.y & 7;
    const int RS = 3 * D_;

    // ---- load Q tile [128][64] hi/lo ----
    {
        const int r_ = tid >> 3, sg = tid & 7;
        #pragma unroll
        for (int i = 0; i < 4; i++) {
            int r = r_ + 32*i;
            size_t g = (size_t)(b*S_ + q0 + r)*RS + h*DH + sg*8;
            cp16(sb + A_QH + r*AST + sg*16, qh + g);
            cp16(sb + A_QL + r*AST + sg*16, ql + g);
        }
    }

    // ---- KV tile loader ----
    auto load_kv = [&](int j, int s) {
        const int r_ = tid >> 3, sg = tid & 7;
        #pragma unroll
        for (int i = 0; i < 2; i++) {
            int r = r_ + 32*i;
            size_t gk = (size_t)(b*S_ + j*64 + r)*RS + D_   + h*DH + sg*8;
            size_t gv = (size_t)(b*S_ + j*64 + r)*RS + 2*D_ + h*DH + sg*8;
            uint32_t so = s*9216 + r*AST + sg*16;
            cp16(sb + A_KH + so, qh + gk);
            cp16(sb + A_KL + so, ql + gk);
            cp16(sb + A_VH + so, qh + gv);
            cp16(sb + A_VL + so, ql + gv);
        }
        if (tid < 64) kvm[s*64 + tid] = mask[b*S_ + j*64 + tid];
    };
    load_kv(0, 0);
    asm volatile("cp.async.commit_group;" ::: "memory");

    if (tid < 128) { m_s[tid] = -INFINITY; l_s[tid] = 0.f; }

    float oacc[2][4][4];
    #pragma unroll
    for (int i = 0; i < 2; i++)
        #pragma unroll
        for (int j = 0; j < 4; j++)
            #pragma unroll
            for (int k = 0; k < 4; k++) oacc[i][j][k] = 0.f;

    const uint32_t lrow = lane & 15;
    const uint32_t lcol = (lane >> 4) * 16;
    const int qr  = lane >> 2;        // row-within-8 for C fragments
    const int cc2 = (lane & 3) * 2;   // col pair base

    for (int j = 0; j < S_/64; j++) {
        const int s = j & 1;
        asm volatile("cp.async.wait_group 0;" ::: "memory");
        __syncthreads();
        if (j + 1 < S_/64) {
            load_kv(j + 1, s ^ 1);
            asm volatile("cp.async.commit_group;" ::: "memory");
        }

        // ---- S = Q K^T (3-term split) ----
        float sacc[2][4][4];
        #pragma unroll
        for (int i = 0; i < 2; i++)
            #pragma unroll
            for (int jj = 0; jj < 4; jj++)
                #pragma unroll
                for (int k = 0; k < 4; k++) sacc[i][jj][k] = 0.f;

        #pragma unroll
        for (int ks = 0; ks < 4; ks++) {           // dh = 64 -> 4 k16 steps
            const uint32_t kb = ks*32 + lcol;
            uint32_t aH[2][4], aL[2][4], bH[4][2], bL[4][2];
            #pragma unroll
            for (int mt = 0; mt < 2; mt++) {
                uint32_t ad = sb + (wm*32 + mt*16 + lrow)*AST + kb;
                ldsm4(aH[mt], ad + A_QH);
                ldsm4(aL[mt], ad + A_QL);
            }
            #pragma unroll
            for (int g = 0; g < 2; g++) {
                uint32_t bd = sb + s*9216 + (wn*32 + g*16 + lrow)*AST + kb;
                uint32_t t0[4], t1[4];
                ldsm4(t0, bd + A_KH);
                ldsm4(t1, bd + A_KL);
                bH[g*2][0] = t0[0]; bH[g*2][1] = t0[2];
                bH[g*2+1][0] = t0[1]; bH[g*2+1][1] = t0[3];
                bL[g*2][0] = t1[0]; bL[g*2][1] = t1[2];
                bL[g*2+1][0] = t1[1]; bL[g*2+1][1] = t1[3];
            }
            #pragma unroll
            for (int mt = 0; mt < 2; mt++)
                #pragma unroll
                for (int nt = 0; nt < 4; nt++) {
                    mma_bf16(sacc[mt][nt], aH[mt], bH[nt]);
                    mma_bf16(sacc[mt][nt], aH[mt], bL[nt]);
                    mma_bf16(sacc[mt][nt], aL[mt], bH[nt]);
                }
        }

        // ---- key mask ----
        #pragma unroll
        for (int nt = 0; nt < 4; nt++)
            #pragma unroll
            for (int jj = 0; jj < 2; jj++) {
                int col = wn*32 + nt*8 + cc2 + jj;
                float mval = (kvm[s*64 + col] == 0) ? -INFINITY : 0.f;
                #pragma unroll
                for (int mt = 0; mt < 2; mt++) {
                    sacc[mt][nt][jj]   += mval;
                    sacc[mt][nt][2+jj] += mval;
                }
            }

        // ---- online softmax: row max ----
        #pragma unroll
        for (int mt = 0; mt < 2; mt++)
            #pragma unroll
            for (int half = 0; half < 2; half++) {
                int row = wm*32 + mt*16 + half*8 + qr;
                float v = -INFINITY;
                #pragma unroll
                for (int nt = 0; nt < 4; nt++) {
                    v = fmaxf(v, sacc[mt][nt][2*half]);
                    v = fmaxf(v, sacc[mt][nt][2*half+1]);
                }
                v = fmaxf(v, __shfl_xor_sync(0xffffffffu, v, 1));
                v = fmaxf(v, __shfl_xor_sync(0xffffffffu, v, 2));
                if ((lane & 3) == 0) pm[wn*128 + row] = v;
            }
        __syncthreads();

        // ---- exp, P store (bf16 hi/lo), row sums, rescale factors ----
        float cloc[2][2], mnew[2][2];
        #pragma unroll
        for (int mt = 0; mt < 2; mt++)
            #pragma unroll
            for (int half = 0; half < 2; half++) {
                int row = wm*32 + mt*16 + half*8 + qr;
                float mo = m_s[row];
                float mn = fmaxf(mo, fmaxf(pm[row], pm[128 + row]));
                mnew[mt][half] = mn;
                float rsum = 0.f;
                #pragma unroll
                for (int nt = 0; nt < 4; nt++) {
                    float p0, p1;
                    if (mn == -INFINITY) { p0 = 0.f; p1 = 0.f; }
                    else {
                        p0 = __expf(sacc[mt][nt][2*half]   - mn);
                        p1 = __expf(sacc[mt][nt][2*half+1] - mn);
                    }
                    rsum += p0 + p1;
                    int col = wn*32 + nt*8 + cc2;
                    ushort2 hh, ll;
                    bf16_split(p0, hh.x, ll.x);
                    bf16_split(p1, hh.y, ll.y);
                    uint32_t po = row*AST + col*2;
                    *(ushort2*)(asmem + A_PH + po) = hh;
                    *(ushort2*)(asmem + A_PL + po) = ll;
                }
                rsum += __shfl_xor_sync(0xffffffffu, rsum, 1);
                rsum += __shfl_xor_sync(0xffffffffu, rsum, 2);
                if ((lane & 3) == 0) ps[wn*128 + row] = rsum;
                cloc[mt][half] = (mn == -INFINITY) ? 1.f : __expf(mo - mn);
            }
        __syncthreads();

        // ---- owner updates m/l state ----
        if (wn == 0 && (lane & 3) == 0) {
            #pragma unroll
            for (int mt = 0; mt < 2; mt++)
                #pragma unroll
                for (int half = 0; half < 2; half++) {
                    int row = wm*32 + mt*16 + half*8 + qr;
                    l_s[row] = l_s[row]*cloc[mt][half] + ps[row] + ps[128 + row];
                    m_s[row] = mnew[mt][half];
                }
        }

        // ---- rescale o ----
        #pragma unroll
        for (int mt = 0; mt < 2; mt++)
            #pragma unroll
            for (int nt = 0; nt < 4; nt++) {
                oacc[mt][nt][0] *= cloc[mt][0];
                oacc[mt][nt][1] *= cloc[mt][0];
                oacc[mt][nt][2] *= cloc[mt][1];
                oacc[mt][nt][3] *= cloc[mt][1];
            }

        // ---- O += P V (3-term split) ----
        #pragma unroll
        for (int ks = 0; ks < 4; ks++) {           // 64 keys -> 4 k16 steps
            const uint32_t kb = ks*32 + lcol;
            uint32_t pHf[2][4], pLf[2][4], vHf[4][2], vLf[4][2];
            #pragma unroll
            for (int mt = 0; mt < 2; mt++) {
                uint32_t ad = sb + (wm*32 + mt*16 + lrow)*AST + kb;
                ldsm4(pHf[mt], ad + A_PH);
                ldsm4(pLf[mt], ad + A_PL);
            }
            #pragma unroll
            for (int g = 0; g < 2; g++) {
                uint32_t va = sb + s*9216
                            + (ks*16 + (lane & 7) + 8*((lane >> 3) & 1))*AST
                            + (wn*32 + g*16 + 8*(lane >> 4))*2;
                uint32_t t0[4], t1[4];
                ldsm4t(t0, va + A_VH);
                ldsm4t(t1, va + A_VL);
                vHf[g*2][0] = t0[0]; vHf[g*2][1] = t0[1];
                vHf[g*2+1][0] = t0[2]; vHf[g*2+1][1] = t0[3];
                vLf[g*2][0] = t1[0]; vLf[g*2][1] = t1[1];
                vLf[g*2+1][0] = t1[2]; vLf[g*2+1][1] = t1[3];
            }
            #pragma unroll
            for (int mt = 0; mt < 2; mt++)
                #pragma unroll
                for (int nt = 0; nt < 4; nt++) {
                    mma_bf16(oacc[mt][nt], pHf[mt], vHf[nt]);
                    mma_bf16(oacc[mt][nt], pHf[mt], vLf[nt]);
                    mma_bf16(oacc[mt][nt], pLf[mt], vHf[nt]);
                }
        }
    }
    __syncthreads();

    // ---- finalize: divide by l, write bf16 hi/lo ----
    #pragma unroll
    for (int mt = 0; mt < 2; mt++)
        #pragma unroll
        for (int half = 0; half < 2; half++) {
            int row = wm*32 + mt*16 + half*8 + qr;
            float linv = 1.f / l_s[row];
            size_t base = (size_t)(b*S_ + q0 + row)*D_ + h*DH;
            #pragma unroll
            for (int nt = 0; nt < 4; nt++) {
                int d = wn*32 + nt*8 + cc2;
                float w0 = oacc[mt][nt][2*half]   * linv;
                float w1 = oacc[mt][nt][2*half+1] * linv;
                ushort2 hh, ll;
                bf16_split(w0, hh.x, ll.x);
                bf16_split(w1, hh.y, ll.y);
                *(ushort2*)&outh[base + d] = hh;
                *(ushort2*)&outl[base + d] = ll;
            }
        }
}

// ============================================================================
// LayerNorm over last dim (512); optional bf16 hi/lo side outputs
// ============================================================================
template<bool SPLIT>
__global__ void __launch_bounds__(256)
ln_kernel(const float* __restrict__ X, const float* __restrict__ g,
          const float* __restrict__ bta, float* __restrict__ Y,
          unsigned short* __restrict__ Yh, unsigned short* __restrict__ Yl)
{
    __shared__ float red[32];
    const int row = blockIdx.x;
    const int t = threadIdx.x;
    const int lane = t & 31, w = t >> 5;

    float2 v = ((const float2*)(X + (size_t)row*D_))[t];

    float s = v.x + v.y;
    #pragma unroll
    for (int o = 16; o; o >>= 1) s += __shfl_xor_sync(0xffffffffu, s, o);
    if (lane == 0) red[w] = s;
    __syncthreads();
    if (t < 32) {
        float a = (t < 8) ? red[t] : 0.f;
        #pragma unroll
        for (int o = 4; o; o >>= 1) a += __shfl_xor_sync(0xffffffffu, a, o);
        if (t == 0) red[0] = a;
    }
    __syncthreads();
    const float mu = red[0] * (1.f / D_);
    __syncthreads();

    float d0 = v.x - mu, d1 = v.y - mu;
    float q = d0*d0 + d1*d1;
    #pragma unroll
    for (int o = 16; o; o >>= 1) q += __shfl_xor_sync(0xffffffffu, q, o);
    if (lane == 0) red[w] = q;
    __syncthreads();
    if (t < 32) {
        float a = (t < 8) ? red[t] : 0.f;
        #pragma unroll
        for (int o = 4; o; o >>= 1) a += __shfl_xor_sync(0xffffffffu, a, o);
        if (t == 0) red[0] = a;
    }
    __syncthreads();
    const float var = red[0] * (1.f / D_);
    const float inv = rsqrtf(var + 1e-5f);

    float2 gv = ((const float2*)g)[t];
    float2 bv = ((const float2*)bta)[t];
    float y0 = d0 * inv * gv.x + bv.x;
    float y1 = d1 * inv * gv.y + bv.y;
    float2 o2; o2.x = y0; o2.y = y1;
    ((float2*)(Y + (size_t)row*D_))[t] = o2;
    if (SPLIT) {
        ushort2 hh, ll;
        bf16_split(y0, hh.x, ll.x);
        bf16_split(y1, hh.y, ll.y);
        ((ushort2*)(Yh + (size_t)row*D_))[t] = hh;
        ((ushort2*)(Yl + (size_t)row*D_))[t] = ll;
    }
}

// ============================================================================
// Host launcher
// ============================================================================
extern "C" void kernel_launch(void* const* d_in, const int* in_sizes, int n_in,
                              void* d_out, int out_size)
{
    const float* x_in  = (const float*)d_in[0];
    const int*   mask  = (const int*)d_in[3];
    const float* Wqkv  = (const float*)d_in[4];
    const float* Wfc   = (const float*)d_in[5];
    const float* bfc   = (const float*)d_in[6];
    const float* ln1g  = (const float*)d_in[7];
    const float* ln1b  = (const float*)d_in[8];
    const float* ln2g  = (const float*)d_in[9];
    const float* ln2b  = (const float*)d_in[10];
    const float* W1    = (const float*)d_in[11];
    const float* b1    = (const float*)d_in[12];
    const float* W2    = (const float*)d_in[13];
    const float* b2    = (const float*)d_in[14];
    float* out = (float*)d_out;

    float *px, *pt;
    unsigned short *pqh, *pql, *pxh, *pxl, *pah, *pal, *phh, *phl, *pwh, *pwl;
    cudaGetSymbolAddress((void**)&px,   g_x);
    cudaGetSymbolAddress((void**)&pt,   g_t);
    cudaGetSymbolAddress((void**)&pqh,  g_qh);
    cudaGetSymbolAddress((void**)&pql,  g_ql);
    cudaGetSymbolAddress((void**)&pxh,  g_xh);
    cudaGetSymbolAddress((void**)&pxl,  g_xl);
    cudaGetSymbolAddress((void**)&pah,  g_ah);
    cudaGetSymbolAddress((void**)&pal,  g_al);
    cudaGetSymbolAddress((void**)&phh,  g_hh);
    cudaGetSymbolAddress((void**)&phl,  g_hl);
    cudaGetSymbolAddress((void**)&pwh,  g_wth);
    cudaGetSymbolAddress((void**)&pwl,  g_wtl);

    const int GSM = 2 * STG_B;   // 80 KB
    cudaFuncSetAttribute(gemm_mma<1>, cudaFuncAttributeMaxDynamicSharedMemorySize, GSM);
    cudaFuncSetAttribute(gemm_mma<2>, cudaFuncAttributeMaxDynamicSharedMemorySize, GSM);
    cudaFuncSetAttribute(gemm_mma<3>, cudaFuncAttributeMaxDynamicSharedMemorySize, GSM);
    cudaFuncSetAttribute(attn_mma, cudaFuncAttributeMaxDynamicSharedMemorySize, A_TOT);

    // weight transpose + bf16 split (all layers)
    transpose_split_kernel<<<dim3(1536/32, 512/32, L_), dim3(32,8)>>>(Wqkv, pwh, pwl, 512, 1536, OFF_QKV);
    transpose_split_kernel<<<dim3( 512/32, 512/32, L_), dim3(32,8)>>>(Wfc,  pwh, pwl, 512,  512, OFF_FC);
    transpose_split_kernel<<<dim3(2048/32, 512/32, L_), dim3(32,8)>>>(W1,   pwh, pwl, 512, 2048, OFF_W1);
    transpose_split_kernel<<<dim3( 512/32,2048/32, L_), dim3(32,8)>>>(W2,   pwh, pwl, 2048, 512, OFF_W2);

    // position embedding
    pos_scan_kernel<<<B_, S_>>>(mask);
    add_pos_kernel<<<(M_*D_)/256, 256>>>(x_in);

    for (int l = 0; l < L_; l++) {
        const unsigned short* wqh = pwh + (size_t)l*WT_L + OFF_QKV;
        const unsigned short* wql = pwl + (size_t)l*WT_L + OFF_QKV;
        const unsigned short* wfh = pwh + (size_t)l*WT_L + OFF_FC;
        const unsigned short* wfl = pwl + (size_t)l*WT_L + OFF_FC;
        const unsigned short* w1h = pwh + (size_t)l*WT_L + OFF_W1;
        const unsigned short* w1l = pwl + (size_t)l*WT_L + OFF_W1;
        const unsigned short* w2h = pwh + (size_t)l*WT_L + OFF_W2;
        const unsigned short* w2l = pwl + (size_t)l*WT_L + OFF_W2;

        // qkv = x @ Wqkv  [8192,512]x[512,1536] -> bf16 hi/lo
        gemm_mma<3><<<dim3(12, 64), 256, GSM>>>(pxh, pxl, wqh, wql,
            nullptr, nullptr, nullptr, pqh, pql, 3*D_, D_);

        // attention (tensor-core flash) -> att bf16 hi/lo
        attn_mma<<<dim3(S_/128, B_*H_), 256, A_TOT>>>(pqh, pql, mask, pah, pal);

        // o @ Wfc + bfc + residual(x) -> t ; LN1 -> x (+hi/lo)
        gemm_mma<1><<<dim3(4, 64), 256, GSM>>>(pah, pal, wfh, wfl,
            bfc + (size_t)l*D_, px, pt, nullptr, nullptr, D_, D_);
        ln_kernel<true><<<M_, 256>>>(pt, ln1g + (size_t)l*D_, ln1b + (size_t)l*D_,
                                     px, pxh, pxl);

        // h = relu(x @ W1 + b1) -> bf16 hi/lo
        gemm_mma<2><<<dim3(16, 64), 256, GSM>>>(pxh, pxl, w1h, w1l,
            b1 + (size_t)l*FF_, nullptr, nullptr, phh, phl, FF_, D_);

        // h @ W2 + b2 + residual(x) -> t ; LN2 -> x (+hi/lo) or d_out
        gemm_mma<1><<<dim3(4, 64), 256, GSM>>>(phh, phl, w2h, w2l,
            b2 + (size_t)l*D_, px, pt, nullptr, nullptr, D_, FF_);
        if (l == L_-1)
            ln_kernel<false><<<M_, 256>>>(pt, ln2g + (size_t)l*D_, ln2b + (size_t)l*D_,
                                          out, nullptr, nullptr);
        else
            ln_kernel<true><<<M_, 256>>>(pt, ln2g + (size_t)l*D_, ln2b + (size_t)l*D_,
                                         px, pxh, pxl);
    }
}